// round 4
// baseline (speedup 1.0000x reference)
#include <cuda_runtime.h>
#include <cstdint>

// ---------------------------------------------------------------------------
// InputStem R4: R3 + (1) conv weight loads as LDS.128 co-quads,
// (2) coalesced GEMM weight staging. Everything else identical to R3.
// ---------------------------------------------------------------------------

#define VOL_FULL (128*128*128)
#define VOL_HALF (64*64*64)
#define N_PATCH  343
#define N_T      160
#define PDIM     131072

typedef unsigned long long u64;

__device__ float  g_buf1[2*16*VOL_FULL];
__device__ float  g_buf2[2*16*VOL_FULL];
__device__ float  g_buf3[2*32*VOL_HALF];
__device__ double g_redp[3][64][64];
__device__ float  g_sbt[3][64];
__device__ float  g_gemm[2*N_PATCH*N_T];

__device__ __forceinline__ float* bufptr(int sel) {
    return sel == 0 ? g_buf1 : (sel == 1 ? g_buf2 : g_buf3);
}

__device__ __forceinline__ u64 pk2(float x, float y) {
    u64 r; asm("mov.b64 %0,{%1,%2};" : "=l"(r) : "f"(x), "f"(y)); return r;
}
__device__ __forceinline__ float2 upk(u64 v) {
    float2 r; asm("mov.b64 {%0,%1},%2;" : "=f"(r.x), "=f"(r.y) : "l"(v)); return r;
}
__device__ __forceinline__ void fma2(u64& d, u64 a, u64 b) {
    asm("fma.rn.f32x2 %0,%1,%2,%0;" : "+l"(d) : "l"(a), "l"(b));
}

// ---------------------------------------------------------------------------
__global__ void k_zero() {
    int i = blockIdx.x * blockDim.x + threadIdx.x;
    if (i < 2*N_PATCH*N_T) g_gemm[i] = 0.f;
    if (i < 3*64*64) ((double*)g_redp)[i] = 0.0;
}

// ---------------------------------------------------------------------------
// stride-1 3x3x3 conv, CI -> 16. Block = TWO output y-rows, 128 thr:
// warp g owns co 4g..4g+3 (2 f32x2 pairs via one LDS.128), lane l owns x 4l..4l+3.
template<int CI, bool APPLY>
__global__ void __launch_bounds__(128) k_conv_s1(
    const float* __restrict__ in_ext, const float* __restrict__ w,
    int in_sel, int out_sel, int stage_in, int stage_out)
{
    __shared__ __align__(16) float sm_in[13*128];   // 12 rows x 132 = 1584 used
    __shared__ __align__(16) float sm_w[CI*27*16];
    const int y0 = 2*blockIdx.x, z = blockIdx.y, b = blockIdx.z;
    const int t = threadIdx.x, l = t & 31, g = t >> 5;
    const float* in = (in_sel < 0) ? in_ext : bufptr(in_sel);
    float* out = bufptr(out_sel);

    for (int i = t; i < CI*27*16; i += 128) {
        int co = i & 15, r = i >> 4, k = r % 27, ci = r / 27;
        sm_w[i] = w[(co*CI + ci)*27 + k];
    }

    int gOff[13];
#pragma unroll
    for (int j = 0; j < 13; j++) {
        int i = t + 128*j, off = -1;
        if (i < 1584) {
            int r = i / 132, idx = i - 132*r;
            int gz = z - 1 + (r >> 2), gy = y0 - 1 + (r & 3), gx = idx - 1;
            if ((unsigned)gz < 128u && (unsigned)gy < 128u && (unsigned)gx < 128u)
                off = (gz*128 + gy)*128 + gx;
        }
        gOff[j] = off;
    }

    u64 acc[2][2][4];
#pragma unroll
    for (int yr = 0; yr < 2; yr++)
#pragma unroll
        for (int j2 = 0; j2 < 2; j2++)
#pragma unroll
            for (int xx = 0; xx < 4; xx++) acc[yr][j2][xx] = 0ULL;

    for (int ci = 0; ci < CI; ci++) {
        float s_ = 1.f, b_ = 0.f;
        if (APPLY) { s_ = g_sbt[stage_in][ci]; b_ = g_sbt[stage_in][32+ci]; }
        const float* inc = in + (size_t)(b*CI + ci) * VOL_FULL;
        __syncthreads();
#pragma unroll
        for (int j = 0; j < 13; j++) {
            int off = gOff[j];
            float v = 0.f;
            if (off >= 0) {
                v = inc[off];
                if (APPLY) v = fmaxf(fmaf(v, s_, b_), 0.f);
            }
            sm_in[t + 128*j] = v;
        }
        __syncthreads();

        const float* wci = sm_w + ci*432;
#pragma unroll
        for (int r = 0; r < 12; r++) {
            float4 A = *(const float4*)(sm_in + r*132 + 4*l);
            float4 B = *(const float4*)(sm_in + r*132 + 4*l + 4);
            float a[7] = {A.x, A.y, A.z, A.w, B.x, B.y, B.z};
            u64 pv[7];
#pragma unroll
            for (int j = 0; j < 7; j++) pv[j] = pk2(a[j], a[j]);
            const int dz = r >> 2, m = r & 3;
#pragma unroll
            for (int yr = 0; yr < 2; yr++) {
                const int dyy = m - yr;
                if (dyy < 0 || dyy > 2) continue;       // compile-time
                const int kb = dz*9 + dyy*3;
#pragma unroll
                for (int dx = 0; dx < 3; dx++) {
                    ulonglong2 wp = *(const ulonglong2*)(wci + (kb+dx)*16 + g*4);
#pragma unroll
                    for (int xx = 0; xx < 4; xx++) {
                        fma2(acc[yr][0][xx], pv[dx+xx], wp.x);
                        fma2(acc[yr][1][xx], pv[dx+xx], wp.y);
                    }
                }
            }
        }
    }

    float2 v[2][2][4];
#pragma unroll
    for (int yr = 0; yr < 2; yr++)
#pragma unroll
        for (int j2 = 0; j2 < 2; j2++)
#pragma unroll
            for (int xx = 0; xx < 4; xx++) v[yr][j2][xx] = upk(acc[yr][j2][xx]);

#pragma unroll
    for (int yr = 0; yr < 2; yr++)
#pragma unroll
        for (int j2 = 0; j2 < 2; j2++) {
            int co = g*4 + 2*j2;
            float4 lo = make_float4(v[yr][j2][0].x, v[yr][j2][1].x, v[yr][j2][2].x, v[yr][j2][3].x);
            float4 hi = make_float4(v[yr][j2][0].y, v[yr][j2][1].y, v[yr][j2][2].y, v[yr][j2][3].y);
            size_t base = (size_t)(b*16 + co)*VOL_FULL + z*16384 + (y0+yr)*128 + 4*l;
            *(float4*)(out + base) = lo;
            *(float4*)(out + base + VOL_FULL) = hi;
        }

#pragma unroll
    for (int c = 0; c < 4; c++) {
        float s = 0.f, q = 0.f;
#pragma unroll
        for (int yr = 0; yr < 2; yr++)
#pragma unroll
            for (int xx = 0; xx < 4; xx++) {
                float val = (c & 1) ? v[yr][c>>1][xx].y : v[yr][c>>1][xx].x;
                s += val; q = fmaf(val, val, q);
            }
#pragma unroll
        for (int o = 16; o; o >>= 1) {
            s += __shfl_down_sync(0xffffffffu, s, o);
            q += __shfl_down_sync(0xffffffffu, q, o);
        }
        if (l == 0) {
            atomicAdd(&g_redp[stage_out][z & 63][g*4 + c],      (double)s);
            atomicAdd(&g_redp[stage_out][z & 63][32 + g*4 + c], (double)q);
        }
    }
}

// ---------------------------------------------------------------------------
// stride-2 3x3x3 conv, 16 -> 32. Block = TWO output y-rows.
// warp g owns co 8g..8g+7 (4 pairs via two LDS.128), lane l owns x 2l, 2l+1.
__global__ void __launch_bounds__(128) k_conv_s2(const float* __restrict__ w)
{
    __shared__ __align__(16) float sm_in[16*128];   // 15 rows x 132 = 1980 used
    __shared__ __align__(16) float sm_w[27*32];
    const int bx = blockIdx.x, z = blockIdx.y, b = blockIdx.z;
    const int t = threadIdx.x, l = t & 31, g = t >> 5;

    int gOff[16];
#pragma unroll
    for (int j = 0; j < 16; j++) {
        int i = t + 128*j, off = -1;
        if (i < 1980) {
            int r = i / 132, idx = i - 132*r;
            int dzr = r / 5, m = r - 5*dzr;
            int gz = 2*z - 1 + dzr, gy = 4*bx - 1 + m, gx = idx - 1;
            if ((unsigned)gz < 128u && (unsigned)gy < 128u && (unsigned)gx < 128u)
                off = (gz*128 + gy)*128 + gx;
        }
        gOff[j] = off;
    }

    u64 acc[2][4][2];
#pragma unroll
    for (int yr = 0; yr < 2; yr++)
#pragma unroll
        for (int j2 = 0; j2 < 4; j2++) { acc[yr][j2][0] = 0ULL; acc[yr][j2][1] = 0ULL; }

    for (int ci = 0; ci < 16; ci++) {
        const float s_ = g_sbt[1][ci], b_ = g_sbt[1][32+ci];
        __syncthreads();
        for (int i = t; i < 864; i += 128) {
            int co = i & 31, k = i >> 5;
            sm_w[k*32 + co] = w[(co*16 + ci)*27 + k];
        }
        const float* inc = g_buf2 + (size_t)(b*16 + ci) * VOL_FULL;
#pragma unroll
        for (int j = 0; j < 16; j++) {
            int off = gOff[j];
            float v = 0.f;
            if (off >= 0)
                v = fmaxf(fmaf(inc[off], s_, b_), 0.f);
            sm_in[t + 128*j] = v;
        }
        __syncthreads();

#pragma unroll
        for (int r = 0; r < 15; r++) {
            float4 A = *(const float4*)(sm_in + r*132 + 4*l);
            float a4 = sm_in[r*132 + 4*l + 4];
            float a[5] = {A.x, A.y, A.z, A.w, a4};
            u64 pv[5];
#pragma unroll
            for (int j = 0; j < 5; j++) pv[j] = pk2(a[j], a[j]);
            const int dzr = r / 5, m = r - 5*dzr;
#pragma unroll
            for (int yr = 0; yr < 2; yr++) {
                const int dyy = m - 2*yr;
                if (dyy < 0 || dyy > 2) continue;       // compile-time
                const int kb = dzr*9 + dyy*3;
#pragma unroll
                for (int dx = 0; dx < 3; dx++) {
                    ulonglong2 wA = *(const ulonglong2*)(sm_w + (kb+dx)*32 + g*8);
                    ulonglong2 wB = *(const ulonglong2*)(sm_w + (kb+dx)*32 + g*8 + 4);
                    fma2(acc[yr][0][0], pv[dx],   wA.x);
                    fma2(acc[yr][0][1], pv[dx+2], wA.x);
                    fma2(acc[yr][1][0], pv[dx],   wA.y);
                    fma2(acc[yr][1][1], pv[dx+2], wA.y);
                    fma2(acc[yr][2][0], pv[dx],   wB.x);
                    fma2(acc[yr][2][1], pv[dx+2], wB.x);
                    fma2(acc[yr][3][0], pv[dx],   wB.y);
                    fma2(acc[yr][3][1], pv[dx+2], wB.y);
                }
            }
        }
    }

    float2 v[2][4][2];
#pragma unroll
    for (int yr = 0; yr < 2; yr++)
#pragma unroll
        for (int j2 = 0; j2 < 4; j2++) {
            v[yr][j2][0] = upk(acc[yr][j2][0]);
            v[yr][j2][1] = upk(acc[yr][j2][1]);
        }

#pragma unroll
    for (int yr = 0; yr < 2; yr++)
#pragma unroll
        for (int j2 = 0; j2 < 4; j2++) {
            int co = g*8 + 2*j2;
            size_t base = (size_t)(b*32 + co)*VOL_HALF + z*4096 + (2*bx+yr)*64 + 2*l;
            *(float2*)(g_buf3 + base) = make_float2(v[yr][j2][0].x, v[yr][j2][1].x);
            *(float2*)(g_buf3 + base + VOL_HALF) = make_float2(v[yr][j2][0].y, v[yr][j2][1].y);
        }

#pragma unroll
    for (int c = 0; c < 8; c++) {
        float s = 0.f, q = 0.f;
#pragma unroll
        for (int yr = 0; yr < 2; yr++)
#pragma unroll
            for (int xx = 0; xx < 2; xx++) {
                float val = (c & 1) ? v[yr][c>>1][xx].y : v[yr][c>>1][xx].x;
                s += val; q = fmaf(val, val, q);
            }
#pragma unroll
        for (int o = 16; o; o >>= 1) {
            s += __shfl_down_sync(0xffffffffu, s, o);
            q += __shfl_down_sync(0xffffffffu, q, o);
        }
        if (l == 0) {
            atomicAdd(&g_redp[2][z & 63][g*8 + c],      (double)s);
            atomicAdd(&g_redp[2][z & 63][32 + g*8 + c], (double)q);
        }
    }
}

// ---------------------------------------------------------------------------
__global__ void k_finalize(int stage, int C, float invN,
                           const float* __restrict__ g,
                           const float* __restrict__ b)
{
    int c = threadIdx.x;
    if (c < C) {
        double s = 0.0, q = 0.0;
        for (int i = 0; i < 64; i++) {
            s += g_redp[stage][i][c];
            q += g_redp[stage][i][32 + c];
        }
        double mean = s * (double)invN;
        double var  = q * (double)invN - mean*mean;
        float sc = g[c] * rsqrtf((float)var + 1e-5f);
        g_sbt[stage][c]      = sc;
        g_sbt[stage][32 + c] = b[c] - (float)mean * sc;
    }
}

// ---------------------------------------------------------------------------
// split-K patch GEMM. Block (m=b*7+pz, ci). Plane relaid as [dy][dx][64pad].
// Weight staging now COALESCED: 4 threads per t-row (8 lines/warp-instr).
__global__ void __launch_bounds__(160) k_gemm(const float* __restrict__ tok_w,
                                              const float* __restrict__ aux_w)
{
    extern __shared__ __align__(16) float dsm[];
    float* in_s = dsm;            // 16*16*64 = 16384
    float* sw   = dsm + 16384;    // 16*160   = 2560
    const int m = blockIdx.x, ci = blockIdx.y;
    const int b = m / 7, pz = m - 7*b;
    const int tid = threadIdx.x;
    const int h = (tid >= 80) ? 1 : 0, tg = tid - 80*h;
    const float s_ = g_sbt[2][ci], b_ = g_sbt[2][32 + ci];

    u64 acc[2][12];
#pragma unroll
    for (int ti = 0; ti < 2; ti++)
#pragma unroll
        for (int k = 0; k < 12; k++) acc[ti][k] = 0ULL;
    float accs[2] = {0.f, 0.f};

    for (int dz = 0; dz < 16; dz++) {
        const float* pl = g_buf3 + ((size_t)(b*32 + ci)*64 + 8*pz + dz)*4096;
        __syncthreads();
        for (int i = tid; i < 16384; i += 160) {
            int gi = i >> 6, pp = i & 63;
            float v = 0.f;
            if (pp < 49) {
                int py = pp / 7, px = pp - 7*py;
                int dy = gi >> 4, dx = gi & 15;
                v = fmaxf(fmaf(pl[(8*py + dy)*64 + 8*px + dx], s_, b_), 0.f);
            }
            in_s[i] = v;
        }
        __syncthreads();

        for (int dy = 0; dy < 16; dy++) {
            const int pbase = ((ci*16 + dz)*16 + dy)*16;
            // coalesced: 4 consecutive threads read one t-row (4 x float4)
#pragma unroll
            for (int i = tid; i < 640; i += 160) {
                int tt = i >> 2, q = i & 3;
                const float* wrow = (tt < 128)
                    ? tok_w + (size_t)tt * PDIM + pbase
                    : aux_w + (size_t)(tt - 128) * PDIM + pbase;
                float4 wq = *(const float4*)(wrow + 4*q);
                sw[(4*q+0)*160 + tt] = wq.x;
                sw[(4*q+1)*160 + tt] = wq.y;
                sw[(4*q+2)*160 + tt] = wq.z;
                sw[(4*q+3)*160 + tt] = wq.w;
            }
            __syncthreads();

#pragma unroll 4
            for (int dx = 0; dx < 16; dx++) {
                float w0 = sw[dx*160 + tg];
                float w1 = sw[dx*160 + tg + 80];
                u64 w0p = pk2(w0, w0), w1p = pk2(w1, w1);
                const float* row = in_s + (dy*16 + dx)*64 + h*24;
                const ulonglong2* q = (const ulonglong2*)row;
#pragma unroll
                for (int k3 = 0; k3 < 6; k3++) {
                    ulonglong2 pr = q[k3];
                    fma2(acc[0][2*k3],   pr.x, w0p);
                    fma2(acc[0][2*k3+1], pr.y, w0p);
                    fma2(acc[1][2*k3],   pr.x, w1p);
                    fma2(acc[1][2*k3+1], pr.y, w1p);
                }
                if (h) {
                    float a48 = row[24];
                    accs[0] = fmaf(a48, w0, accs[0]);
                    accs[1] = fmaf(a48, w1, accs[1]);
                }
            }
            __syncthreads();
        }
    }

    const int gbase = (b*N_PATCH + pz*49)*N_T;
#pragma unroll
    for (int ti = 0; ti < 2; ti++) {
        int tt = tg + 80*ti;
#pragma unroll
        for (int k = 0; k < 12; k++) {
            float2 u = upk(acc[ti][k]);
            int p = h*24 + 2*k;
            atomicAdd(&g_gemm[gbase + p*N_T + tt],     u.x);
            atomicAdd(&g_gemm[gbase + (p+1)*N_T + tt], u.y);
        }
        if (h) atomicAdd(&g_gemm[gbase + 48*N_T + tt], accs[ti]);
    }
}

// ---------------------------------------------------------------------------
__global__ void k_final(const float* __restrict__ tok_b,
                        const float* __restrict__ aux_b,
                        const float* __restrict__ ln_g,
                        const float* __restrict__ ln_b,
                        float* __restrict__ out)
{
    const int bn = blockIdx.x;
    const int n = bn % N_PATCH;
    const int t = threadIdx.x;

    float v = g_gemm[bn*N_T + t] + tok_b[t];
    float s = v, q = v*v;
#pragma unroll
    for (int o = 16; o; o >>= 1) {
        s += __shfl_down_sync(0xffffffffu, s, o);
        q += __shfl_down_sync(0xffffffffu, q, o);
    }
    __shared__ float ss[4], qq[4];
    int wp = t >> 5, ln = t & 31;
    if (ln == 0) { ss[wp] = s; qq[wp] = q; }
    __syncthreads();
    float S1 = ss[0] + ss[1] + ss[2] + ss[3];
    float S2 = qq[0] + qq[1] + qq[2] + qq[3];
    float mean = S1 * (1.f/128.f);
    float var  = S2 * (1.f/128.f) - mean*mean;
    float r = rsqrtf(var + 1e-5f);

    out[bn*128 + t] = (v - mean) * r * ln_g[t] + ln_b[t];

    if (t < 32)
        out[87808 + bn*32 + t] = g_gemm[bn*N_T + 128 + t] + aux_b[t];

    if (t < 3) {
        int pz = n / 49, py = (n / 7) % 7, px = n % 7;
        float c;
        if      (t == 0) c = ((float)pz * 8.f + 7.5f) * (1.f/63.f);
        else if (t == 1) c = ((float)py * 8.f + 7.5f) * (1.f/63.f);
        else             c = ((float)px * 8.f + 7.5f) * (1.f/63.f);
        out[109760 + bn*3 + t] = c;
    }
}

// ---------------------------------------------------------------------------
extern "C" void kernel_launch(void* const* d_in, const int* in_sizes, int n_in,
                              void* d_out, int out_size) {
    const float* x     = (const float*)d_in[0];
    const float* c1w   = (const float*)d_in[1];
    const float* bn1g  = (const float*)d_in[2];
    const float* bn1b  = (const float*)d_in[3];
    const float* c2w   = (const float*)d_in[4];
    const float* bn2g  = (const float*)d_in[5];
    const float* bn2b  = (const float*)d_in[6];
    const float* c3w   = (const float*)d_in[7];
    const float* bn3g  = (const float*)d_in[8];
    const float* bn3b  = (const float*)d_in[9];
    const float* tokw  = (const float*)d_in[10];
    const float* tokb  = (const float*)d_in[11];
    const float* auxw  = (const float*)d_in[12];
    const float* auxb  = (const float*)d_in[13];
    const float* lng   = (const float*)d_in[14];
    const float* lnb   = (const float*)d_in[15];
    float* out = (float*)d_out;

    const int GEMM_SMEM = (16384 + 2560) * (int)sizeof(float);   // 75776
    cudaFuncSetAttribute(k_gemm, cudaFuncAttributeMaxDynamicSharedMemorySize, GEMM_SMEM);

    k_zero<<<(2*N_PATCH*N_T + 255)/256, 256>>>();

    k_conv_s1<1,  false><<<dim3(64,128,2), 128>>>(x, c1w, -1, 0, 0, 0);
    k_finalize<<<1, 32>>>(0, 16, 1.f/(2.f*VOL_FULL), bn1g, bn1b);

    k_conv_s1<16, true ><<<dim3(64,128,2), 128>>>(nullptr, c2w, 0, 1, 0, 1);
    k_finalize<<<1, 32>>>(1, 16, 1.f/(2.f*VOL_FULL), bn2g, bn2b);

    k_conv_s2<<<dim3(32,64,2), 128>>>(c3w);
    k_finalize<<<1, 32>>>(2, 32, 1.f/(2.f*VOL_HALF), bn3g, bn3b);

    k_gemm<<<dim3(14,32), 160, GEMM_SMEM>>>(tokw, auxw);
    k_final<<<686, 128>>>(tokb, auxb, lng, lnb, out);
}

// round 6
// speedup vs baseline: 1.3488x; 1.3488x over previous
#include <cuda_runtime.h>
#include <cuda_bf16.h>
#include <cstdint>

// ---------------------------------------------------------------------------
// InputStem R6: R3 convs + mma.sync (HMMA) bf16x3 patch GEMM.
// (tcgen05 is unavailable: harness lowers via compute_103 PTX.)
// ---------------------------------------------------------------------------

#define VOL_FULL (128*128*128)
#define VOL_HALF (64*64*64)
#define N_PATCH  343
#define N_T      160
#define PDIM     131072

typedef unsigned long long u64;

__device__ float  g_buf1[2*16*VOL_FULL];
__device__ float  g_buf2[2*16*VOL_FULL];
__device__ float  g_buf3[2*32*VOL_HALF];
__device__ double g_redp[3][64][64];
__device__ float  g_sbt[3][64];
__device__ float  g_gemm[2*N_PATCH*N_T];

// bf16 hi/lo decompositions
__device__ __nv_bfloat16 g_ahi[2*32*VOL_HALF];
__device__ __nv_bfloat16 g_alo[2*32*VOL_HALF];
__device__ __nv_bfloat16 g_whi[(size_t)N_T*PDIM];
__device__ __nv_bfloat16 g_wlo[(size_t)N_T*PDIM];

__device__ __forceinline__ float* bufptr(int sel) {
    return sel == 0 ? g_buf1 : (sel == 1 ? g_buf2 : g_buf3);
}

__device__ __forceinline__ u64 pk2(float x, float y) {
    u64 r; asm("mov.b64 %0,{%1,%2};" : "=l"(r) : "f"(x), "f"(y)); return r;
}
__device__ __forceinline__ float2 upk(u64 v) {
    float2 r; asm("mov.b64 {%0,%1},%2;" : "=f"(r.x), "=f"(r.y) : "l"(v)); return r;
}
__device__ __forceinline__ void fma2(u64& d, u64 a, u64 b) {
    asm("fma.rn.f32x2 %0,%1,%2,%0;" : "+l"(d) : "l"(a), "l"(b));
}

// ---- HMMA helpers ----------------------------------------------------------
__device__ __forceinline__ uint32_t smem_u32(const void* p) {
    uint32_t a;
    asm("{ .reg .u64 t; cvta.to.shared.u64 t, %1; cvt.u32.u64 %0, t; }" : "=r"(a) : "l"(p));
    return a;
}
__device__ __forceinline__ void ldsm4(uint32_t* r, uint32_t addr) {
    asm volatile("ldmatrix.sync.aligned.m8n8.x4.shared.b16 {%0,%1,%2,%3}, [%4];"
        : "=r"(r[0]), "=r"(r[1]), "=r"(r[2]), "=r"(r[3]) : "r"(addr));
}
__device__ __forceinline__ void mma_bf16(float* d, const uint32_t* a,
                                         uint32_t b0, uint32_t b1) {
    asm volatile("mma.sync.aligned.m16n8k16.row.col.f32.bf16.bf16.f32 "
        "{%0,%1,%2,%3}, {%4,%5,%6,%7}, {%8,%9}, {%0,%1,%2,%3};"
        : "+f"(d[0]), "+f"(d[1]), "+f"(d[2]), "+f"(d[3])
        : "r"(a[0]), "r"(a[1]), "r"(a[2]), "r"(a[3]), "r"(b0), "r"(b1));
}

// ---------------------------------------------------------------------------
__global__ void k_zero() {
    int i = blockIdx.x * blockDim.x + threadIdx.x;
    if (i < 2*N_PATCH*N_T) g_gemm[i] = 0.f;
    if (i < 3*64*64) ((double*)g_redp)[i] = 0.0;
}

// ---------------------------------------------------------------------------
// (R3) stride-1 3x3x3 conv, CI -> 16. Block = TWO output y-rows.
template<int CI, bool APPLY>
__global__ void __launch_bounds__(128) k_conv_s1(
    const float* __restrict__ in_ext, const float* __restrict__ w,
    int in_sel, int out_sel, int stage_in, int stage_out)
{
    __shared__ __align__(16) float sm_in[13*128];
    __shared__ float sm_w[CI*27*16];
    const int y0 = 2*blockIdx.x, z = blockIdx.y, b = blockIdx.z;
    const int t = threadIdx.x, l = t & 31, g = t >> 5;
    const float* in = (in_sel < 0) ? in_ext : bufptr(in_sel);
    float* out = bufptr(out_sel);

    for (int i = t; i < CI*27*16; i += 128) {
        int co = i & 15, r = i >> 4, k = r % 27, ci = r / 27;
        sm_w[i] = w[(co*CI + ci)*27 + k];
    }

    int gOff[13];
#pragma unroll
    for (int j = 0; j < 13; j++) {
        int i = t + 128*j, off = -1;
        if (i < 1584) {
            int r = i / 132, idx = i - 132*r;
            int gz = z - 1 + (r >> 2), gy = y0 - 1 + (r & 3), gx = idx - 1;
            if ((unsigned)gz < 128u && (unsigned)gy < 128u && (unsigned)gx < 128u)
                off = (gz*128 + gy)*128 + gx;
        }
        gOff[j] = off;
    }

    u64 acc[2][2][4];
#pragma unroll
    for (int yr = 0; yr < 2; yr++)
#pragma unroll
        for (int j2 = 0; j2 < 2; j2++)
#pragma unroll
            for (int xx = 0; xx < 4; xx++) acc[yr][j2][xx] = 0ULL;

    for (int ci = 0; ci < CI; ci++) {
        float s_ = 1.f, b_ = 0.f;
        if (APPLY) { s_ = g_sbt[stage_in][ci]; b_ = g_sbt[stage_in][32+ci]; }
        const float* inc = in + (size_t)(b*CI + ci) * VOL_FULL;
        __syncthreads();
#pragma unroll
        for (int j = 0; j < 13; j++) {
            int off = gOff[j];
            float v = 0.f;
            if (off >= 0) {
                v = inc[off];
                if (APPLY) v = fmaxf(fmaf(v, s_, b_), 0.f);
            }
            sm_in[t + 128*j] = v;
        }
        __syncthreads();

        const float* wci = sm_w + ci*432;
#pragma unroll
        for (int r = 0; r < 12; r++) {
            float4 A = *(const float4*)(sm_in + r*132 + 4*l);
            float4 B = *(const float4*)(sm_in + r*132 + 4*l + 4);
            float a[7] = {A.x, A.y, A.z, A.w, B.x, B.y, B.z};
            u64 pv[7];
#pragma unroll
            for (int j = 0; j < 7; j++) pv[j] = pk2(a[j], a[j]);
            const int dz = r >> 2, m = r & 3;
#pragma unroll
            for (int yr = 0; yr < 2; yr++) {
                const int dyy = m - yr;
                if (dyy < 0 || dyy > 2) continue;
                const int kb = dz*9 + dyy*3;
#pragma unroll
                for (int dx = 0; dx < 3; dx++) {
                    u64 w0 = *(const u64*)(wci + (kb+dx)*16 + g*4);
                    u64 w1 = *(const u64*)(wci + (kb+dx)*16 + g*4 + 2);
#pragma unroll
                    for (int xx = 0; xx < 4; xx++) {
                        fma2(acc[yr][0][xx], pv[dx+xx], w0);
                        fma2(acc[yr][1][xx], pv[dx+xx], w1);
                    }
                }
            }
        }
    }

    float2 v[2][2][4];
#pragma unroll
    for (int yr = 0; yr < 2; yr++)
#pragma unroll
        for (int j2 = 0; j2 < 2; j2++)
#pragma unroll
            for (int xx = 0; xx < 4; xx++) v[yr][j2][xx] = upk(acc[yr][j2][xx]);

#pragma unroll
    for (int yr = 0; yr < 2; yr++)
#pragma unroll
        for (int j2 = 0; j2 < 2; j2++) {
            int co = g*4 + 2*j2;
            float4 lo = make_float4(v[yr][j2][0].x, v[yr][j2][1].x, v[yr][j2][2].x, v[yr][j2][3].x);
            float4 hi = make_float4(v[yr][j2][0].y, v[yr][j2][1].y, v[yr][j2][2].y, v[yr][j2][3].y);
            size_t base = (size_t)(b*16 + co)*VOL_FULL + z*16384 + (y0+yr)*128 + 4*l;
            *(float4*)(out + base) = lo;
            *(float4*)(out + base + VOL_FULL) = hi;
        }

#pragma unroll
    for (int c = 0; c < 4; c++) {
        float s = 0.f, q = 0.f;
#pragma unroll
        for (int yr = 0; yr < 2; yr++)
#pragma unroll
            for (int xx = 0; xx < 4; xx++) {
                float val = (c & 1) ? v[yr][c>>1][xx].y : v[yr][c>>1][xx].x;
                s += val; q = fmaf(val, val, q);
            }
#pragma unroll
        for (int o = 16; o; o >>= 1) {
            s += __shfl_down_sync(0xffffffffu, s, o);
            q += __shfl_down_sync(0xffffffffu, q, o);
        }
        if (l == 0) {
            atomicAdd(&g_redp[stage_out][z & 63][g*4 + c],      (double)s);
            atomicAdd(&g_redp[stage_out][z & 63][32 + g*4 + c], (double)q);
        }
    }
}

// ---------------------------------------------------------------------------
// (R3) stride-2 3x3x3 conv, 16 -> 32. Block = TWO output y-rows.
__global__ void __launch_bounds__(128) k_conv_s2(const float* __restrict__ w)
{
    __shared__ __align__(16) float sm_in[16*128];
    __shared__ float sm_w[27*32];
    const int bx = blockIdx.x, z = blockIdx.y, b = blockIdx.z;
    const int t = threadIdx.x, l = t & 31, g = t >> 5;

    int gOff[16];
#pragma unroll
    for (int j = 0; j < 16; j++) {
        int i = t + 128*j, off = -1;
        if (i < 1980) {
            int r = i / 132, idx = i - 132*r;
            int dzr = r / 5, m = r - 5*dzr;
            int gz = 2*z - 1 + dzr, gy = 4*bx - 1 + m, gx = idx - 1;
            if ((unsigned)gz < 128u && (unsigned)gy < 128u && (unsigned)gx < 128u)
                off = (gz*128 + gy)*128 + gx;
        }
        gOff[j] = off;
    }

    u64 acc[2][4][2];
#pragma unroll
    for (int yr = 0; yr < 2; yr++)
#pragma unroll
        for (int j2 = 0; j2 < 4; j2++) { acc[yr][j2][0] = 0ULL; acc[yr][j2][1] = 0ULL; }

    for (int ci = 0; ci < 16; ci++) {
        const float s_ = g_sbt[1][ci], b_ = g_sbt[1][32+ci];
        __syncthreads();
        for (int i = t; i < 864; i += 128) {
            int co = i & 31, k = i >> 5;
            sm_w[k*32 + co] = w[(co*16 + ci)*27 + k];
        }
        const float* inc = g_buf2 + (size_t)(b*16 + ci) * VOL_FULL;
#pragma unroll
        for (int j = 0; j < 16; j++) {
            int off = gOff[j];
            float v = 0.f;
            if (off >= 0)
                v = fmaxf(fmaf(inc[off], s_, b_), 0.f);
            sm_in[t + 128*j] = v;
        }
        __syncthreads();

#pragma unroll
        for (int r = 0; r < 15; r++) {
            float4 A = *(const float4*)(sm_in + r*132 + 4*l);
            float a4 = sm_in[r*132 + 4*l + 4];
            float a[5] = {A.x, A.y, A.z, A.w, a4};
            u64 pv[5];
#pragma unroll
            for (int j = 0; j < 5; j++) pv[j] = pk2(a[j], a[j]);
            const int dzr = r / 5, m = r - 5*dzr;
#pragma unroll
            for (int yr = 0; yr < 2; yr++) {
                const int dyy = m - 2*yr;
                if (dyy < 0 || dyy > 2) continue;
                const int kb = dzr*9 + dyy*3;
#pragma unroll
                for (int dx = 0; dx < 3; dx++) {
#pragma unroll
                    for (int j2 = 0; j2 < 4; j2++) {
                        u64 wv = *(const u64*)(sm_w + (kb+dx)*32 + g*8 + 2*j2);
                        fma2(acc[yr][j2][0], pv[dx],   wv);
                        fma2(acc[yr][j2][1], pv[dx+2], wv);
                    }
                }
            }
        }
    }

    float2 v[2][4][2];
#pragma unroll
    for (int yr = 0; yr < 2; yr++)
#pragma unroll
        for (int j2 = 0; j2 < 4; j2++) {
            v[yr][j2][0] = upk(acc[yr][j2][0]);
            v[yr][j2][1] = upk(acc[yr][j2][1]);
        }

#pragma unroll
    for (int yr = 0; yr < 2; yr++)
#pragma unroll
        for (int j2 = 0; j2 < 4; j2++) {
            int co = g*8 + 2*j2;
            size_t base = (size_t)(b*32 + co)*VOL_HALF + z*4096 + (2*bx+yr)*64 + 2*l;
            *(float2*)(g_buf3 + base) = make_float2(v[yr][j2][0].x, v[yr][j2][1].x);
            *(float2*)(g_buf3 + base + VOL_HALF) = make_float2(v[yr][j2][0].y, v[yr][j2][1].y);
        }

#pragma unroll
    for (int c = 0; c < 8; c++) {
        float s = 0.f, q = 0.f;
#pragma unroll
        for (int yr = 0; yr < 2; yr++)
#pragma unroll
            for (int xx = 0; xx < 2; xx++) {
                float val = (c & 1) ? v[yr][c>>1][xx].y : v[yr][c>>1][xx].x;
                s += val; q = fmaf(val, val, q);
            }
#pragma unroll
        for (int o = 16; o; o >>= 1) {
            s += __shfl_down_sync(0xffffffffu, s, o);
            q += __shfl_down_sync(0xffffffffu, q, o);
        }
        if (l == 0) {
            atomicAdd(&g_redp[2][z & 63][g*8 + c],      (double)s);
            atomicAdd(&g_redp[2][z & 63][32 + g*8 + c], (double)q);
        }
    }
}

// ---------------------------------------------------------------------------
__global__ void k_finalize(int stage, int C, float invN,
                           const float* __restrict__ g,
                           const float* __restrict__ b)
{
    int c = threadIdx.x;
    if (c < C) {
        double s = 0.0, q = 0.0;
        for (int i = 0; i < 64; i++) {
            s += g_redp[stage][i][c];
            q += g_redp[stage][i][32 + c];
        }
        double mean = s * (double)invN;
        double var  = q * (double)invN - mean*mean;
        float sc = g[c] * rsqrtf((float)var + 1e-5f);
        g_sbt[stage][c]      = sc;
        g_sbt[stage][32 + c] = b[c] - (float)mean * sc;
    }
}

// ---------------------------------------------------------------------------
// decompose weights -> bf16 hi/lo (combined t: 128 tok + 32 aux)
__global__ void __launch_bounds__(256) k_decompW(const float* __restrict__ tok_w,
                                                 const float* __restrict__ aux_w)
{
    size_t gid = (size_t)blockIdx.x*256 + threadIdx.x;
    size_t e = gid*8;
    if (e >= (size_t)N_T*PDIM) return;
    int t = (int)(e >> 17);
    int k = (int)(e & (PDIM-1));
    const float* src = (t < 128) ? tok_w + ((size_t)t << 17) + k
                                 : aux_w + ((size_t)(t-128) << 17) + k;
    float4 a = ((const float4*)src)[0];
    float4 c = ((const float4*)src)[1];
    float v[8] = {a.x,a.y,a.z,a.w, c.x,c.y,c.z,c.w};
    __align__(16) __nv_bfloat16 h[8];
    __align__(16) __nv_bfloat16 l[8];
#pragma unroll
    for (int j = 0; j < 8; j++) {
        h[j] = __float2bfloat16(v[j]);
        l[j] = __float2bfloat16(v[j] - __bfloat162float(h[j]));
    }
    *(uint4*)(g_whi + e) = *(uint4*)h;
    *(uint4*)(g_wlo + e) = *(uint4*)l;
}

// decompose BN+ReLU'd conv3 activations -> bf16 hi/lo
__global__ void __launch_bounds__(256) k_decompA()
{
    size_t gid = (size_t)blockIdx.x*256 + threadIdx.x;
    size_t e = gid*8;
    if (e >= (size_t)2*32*VOL_HALF) return;
    int ci = (int)((e >> 18) & 31);
    float s_ = g_sbt[2][ci], b_ = g_sbt[2][32 + ci];
    float4 a = *(const float4*)(g_buf3 + e);
    float4 c = *(const float4*)(g_buf3 + e + 4);
    float v[8] = {a.x,a.y,a.z,a.w, c.x,c.y,c.z,c.w};
    __align__(16) __nv_bfloat16 h[8];
    __align__(16) __nv_bfloat16 l[8];
#pragma unroll
    for (int j = 0; j < 8; j++) {
        float x = fmaxf(fmaf(v[j], s_, b_), 0.f);
        h[j] = __float2bfloat16(x);
        l[j] = __float2bfloat16(x - __bfloat162float(h[j]));
    }
    *(uint4*)(g_ahi + e) = *(uint4*)h;
    *(uint4*)(g_alo + e) = *(uint4*)l;
}

// ---------------------------------------------------------------------------
// HMMA bf16x3 GEMM. Block (tile, ci): M-tile 128 patches x N=160, K = ci's
// 4096 elems in 64 chunks of 64. 8 warps, warp w = rows 16w..16w+15, all N.
// smem rows padded to 72 bf16 (144B) -> conflict-free ldmatrix.
#define A_HI 0
#define A_LO 18432
#define B_HI 36864
#define B_LO 59904
#define GEMM_SMEM 82944

__global__ void __launch_bounds__(256, 2) k_gemm_tc()
{
    extern __shared__ __align__(16) char smem[];
    const uint32_t sb = smem_u32(smem);
    const int tile = blockIdx.x, ci = blockIdx.y;
    const int tid = threadIdx.x, w = tid >> 5, lane = tid & 31;

    // per-thread A-row gather state (threads 0..127 fill A)
    int m = tile*128 + tid;
    bool valid = (tid < 128) && (m < 686);
    int b = 0, pz = 0, py = 0, px = 0;
    if (valid) {
        b = (m >= 343) ? 1 : 0;
        int n = m - 343*b;
        pz = n / 49; int r2 = n - 49*pz;
        py = r2 / 7; px = r2 - 7*py;
    }
    const size_t chan = (size_t)(b*32 + ci)*64;

    // ldmatrix lane bases
    const uint32_t aOff = (uint32_t)((16*w + (lane & 15))*144 + ((lane >> 4)*8)*2);
    const uint32_t aHiB = sb + A_HI + aOff;
    const uint32_t aLoB = sb + A_LO + aOff;
    const uint32_t bOff = (uint32_t)((((lane >> 4) << 3) + (lane & 7))*144
                                     + (((lane >> 3) & 1)*8)*2);
    const uint32_t bHiB = sb + B_HI + bOff;
    const uint32_t bLoB = sb + B_LO + bOff;

    float d[20][4];
#pragma unroll
    for (int nt = 0; nt < 20; nt++)
#pragma unroll
        for (int i = 0; i < 4; i++) d[nt][i] = 0.f;

    const size_t kcol = (size_t)ci*4096;

    for (int chunk = 0; chunk < 64; chunk++) {
        __syncthreads();   // previous compute done before refill

        // ---- A fill: threads 0..127, row tid = 64 bf16 (4 dy segs of 16)
        if (tid < 128) {
            const int dz = chunk >> 2, dy0 = (chunk & 3) << 2;
#pragma unroll
            for (int j = 0; j < 4; j++) {
                uint4 h0 = make_uint4(0,0,0,0), h1 = h0, l0 = h0, l1 = h0;
                if (valid) {
                    size_t idx = (chan + 8*pz + dz)*4096
                               + (size_t)(8*py + dy0 + j)*64 + 8*px;
                    h0 = *(const uint4*)(g_ahi + idx);
                    h1 = *(const uint4*)(g_ahi + idx + 8);
                    l0 = *(const uint4*)(g_alo + idx);
                    l1 = *(const uint4*)(g_alo + idx + 8);
                }
                int dst = tid*144 + j*32;
                *(uint4*)(smem + A_HI + dst)      = h0;
                *(uint4*)(smem + A_HI + dst + 16) = h1;
                *(uint4*)(smem + A_LO + dst)      = l0;
                *(uint4*)(smem + A_LO + dst + 16) = l1;
            }
        }
        // ---- B fill: all 256 threads, 160 rows x 64 bf16 hi+lo
        {
            const size_t kb = kcol + (size_t)chunk*64;
#pragma unroll
            for (int i = tid; i < 1280; i += 256) {
                int n = i >> 3, seg = i & 7;
                size_t so = (size_t)n*PDIM + kb + seg*8;
                int dst = n*144 + seg*16;
                *(uint4*)(smem + B_HI + dst) = *(const uint4*)(g_whi + so);
                *(uint4*)(smem + B_LO + dst) = *(const uint4*)(g_wlo + so);
            }
        }
        __syncthreads();

        // ---- compute: 4 k16-steps x (Ah,Al) x 10 n-tile-pairs x 3 products
#pragma unroll
        for (int ks = 0; ks < 4; ks++) {
            uint32_t ah[4], al[4];
            ldsm4(ah, aHiB + ks*32);
            ldsm4(al, aLoB + ks*32);
#pragma unroll
            for (int j = 0; j < 10; j++) {
                uint32_t bh[4], bl[4];
                ldsm4(bh, bHiB + j*2304 + ks*32);
                ldsm4(bl, bLoB + j*2304 + ks*32);
                mma_bf16(d[2*j],   ah, bh[0], bh[1]);
                mma_bf16(d[2*j+1], ah, bh[2], bh[3]);
                mma_bf16(d[2*j],   ah, bl[0], bl[1]);
                mma_bf16(d[2*j+1], ah, bl[2], bl[3]);
                mma_bf16(d[2*j],   al, bh[0], bh[1]);
                mma_bf16(d[2*j+1], al, bh[2], bh[3]);
            }
        }
    }

    // ---- epilogue: fragment (quad = lane>>2 row, 2*(lane&3) col), atomics
    const int mr = tile*128 + 16*w + (lane >> 2);
    const int qc = 2*(lane & 3);
#pragma unroll
    for (int nt = 0; nt < 20; nt++) {
        int col = 8*nt + qc;
        if (mr < 686) {
            atomicAdd(&g_gemm[mr*N_T + col],     d[nt][0]);
            atomicAdd(&g_gemm[mr*N_T + col + 1], d[nt][1]);
        }
        if (mr + 8 < 686) {
            atomicAdd(&g_gemm[(mr+8)*N_T + col],     d[nt][2]);
            atomicAdd(&g_gemm[(mr+8)*N_T + col + 1], d[nt][3]);
        }
    }
}

// ---------------------------------------------------------------------------
__global__ void k_final(const float* __restrict__ tok_b,
                        const float* __restrict__ aux_b,
                        const float* __restrict__ ln_g,
                        const float* __restrict__ ln_b,
                        float* __restrict__ out)
{
    const int bn = blockIdx.x;
    const int n = bn % N_PATCH;
    const int t = threadIdx.x;

    float v = g_gemm[bn*N_T + t] + tok_b[t];
    float s = v, q = v*v;
#pragma unroll
    for (int o = 16; o; o >>= 1) {
        s += __shfl_down_sync(0xffffffffu, s, o);
        q += __shfl_down_sync(0xffffffffu, q, o);
    }
    __shared__ float ss[4], qq[4];
    int wp = t >> 5, ln = t & 31;
    if (ln == 0) { ss[wp] = s; qq[wp] = q; }
    __syncthreads();
    float S1 = ss[0] + ss[1] + ss[2] + ss[3];
    float S2 = qq[0] + qq[1] + qq[2] + qq[3];
    float mean = S1 * (1.f/128.f);
    float var  = S2 * (1.f/128.f) - mean*mean;
    float r = rsqrtf(var + 1e-5f);

    out[bn*128 + t] = (v - mean) * r * ln_g[t] + ln_b[t];

    if (t < 32)
        out[87808 + bn*32 + t] = g_gemm[bn*N_T + 128 + t] + aux_b[t];

    if (t < 3) {
        int pz = n / 49, py = (n / 7) % 7, px = n % 7;
        float c;
        if      (t == 0) c = ((float)pz * 8.f + 7.5f) * (1.f/63.f);
        else if (t == 1) c = ((float)py * 8.f + 7.5f) * (1.f/63.f);
        else             c = ((float)px * 8.f + 7.5f) * (1.f/63.f);
        out[109760 + bn*3 + t] = c;
    }
}

// ---------------------------------------------------------------------------
extern "C" void kernel_launch(void* const* d_in, const int* in_sizes, int n_in,
                              void* d_out, int out_size) {
    const float* x     = (const float*)d_in[0];
    const float* c1w   = (const float*)d_in[1];
    const float* bn1g  = (const float*)d_in[2];
    const float* bn1b  = (const float*)d_in[3];
    const float* c2w   = (const float*)d_in[4];
    const float* bn2g  = (const float*)d_in[5];
    const float* bn2b  = (const float*)d_in[6];
    const float* c3w   = (const float*)d_in[7];
    const float* bn3g  = (const float*)d_in[8];
    const float* bn3b  = (const float*)d_in[9];
    const float* tokw  = (const float*)d_in[10];
    const float* tokb  = (const float*)d_in[11];
    const float* auxw  = (const float*)d_in[12];
    const float* auxb  = (const float*)d_in[13];
    const float* lng   = (const float*)d_in[14];
    const float* lnb   = (const float*)d_in[15];
    float* out = (float*)d_out;

    cudaFuncSetAttribute(k_gemm_tc, cudaFuncAttributeMaxDynamicSharedMemorySize,
                         GEMM_SMEM);

    k_zero<<<(2*N_PATCH*N_T + 255)/256, 256>>>();

    // weight decomposition (independent of convs)
    k_decompW<<<(int)(((size_t)N_T*PDIM/8 + 255)/256), 256>>>(tokw, auxw);

    k_conv_s1<1,  false><<<dim3(64,128,2), 128>>>(x, c1w, -1, 0, 0, 0);
    k_finalize<<<1, 32>>>(0, 16, 1.f/(2.f*VOL_FULL), bn1g, bn1b);

    k_conv_s1<16, true ><<<dim3(64,128,2), 128>>>(nullptr, c2w, 0, 1, 0, 1);
    k_finalize<<<1, 32>>>(1, 16, 1.f/(2.f*VOL_FULL), bn2g, bn2b);

    k_conv_s2<<<dim3(32,64,2), 128>>>(c3w);
    k_finalize<<<1, 32>>>(2, 32, 1.f/(2.f*VOL_HALF), bn3g, bn3b);

    // activation decomposition (needs stage-2 BN params)
    k_decompA<<<(int)(((size_t)2*32*VOL_HALF/8 + 255)/256), 256>>>();

    // HMMA bf16x3 patch GEMM (ci-major grid -> weight slice L2-hot)
    k_gemm_tc<<<dim3(6, 32), 256, GEMM_SMEM>>>();

    k_final<<<686, 128>>>(tokb, auxb, lng, lnb, out);
}